// round 5
// baseline (speedup 1.0000x reference)
#include <cuda_runtime.h>
#include <cstdint>

// DeepSeekMoEFFN: top-1 MoE (2 routing experts) + shared expert, fused as
// grouped 2-layer MLP over expert-sorted tokens, tf32 tensor-core GEMMs.
//
// Pipeline (all launches on stream 0, graph-capturable, no allocs):
//  1. zero counters
//  2. gate (fp64 dot + argmax) -> expert id per token, counts
//  3. counting-sort scatter -> perm (sorted token order, group0 then group1)
//  4. preprocess: gather+rna(x), build concat B1=[w1_e|sw1], B2=[w2_e;sw2] (rna),
//     bias1=[b1_e|sb1], bias2 = b2_0 + b2_1 + sb2 + relu(b1_other)@w2_other
//  5. GEMM1: h = rna(relu(xs @ B1_e + bias1_e))  [16384 x 8192]
//  6. GEMM2: out[perm] = h @ B2_e + bias2_e      [16384 x 1024]

#define N_TOK  16384
#define DMODEL 1024
#define HID    4096
#define HCAT   8192

#define BM 128
#define BN 128
#define BK 32
#define SA_LD 133   // padded lds stride for A (odd -> conflict-free STS)
#define SB_LD 136   // padded lds stride for B (+8 -> conflict-free frag LDS)
#define SMEM_BYTES ((2*BK*SA_LD + 2*BK*SB_LD) * 4)

// ---- device scratch (static, no runtime allocation) ----
__device__ float g_h[(size_t)N_TOK * HCAT];        // 512 MB intermediate
__device__ float g_xr[(size_t)N_TOK * DMODEL];     // sorted + tf32-rounded x
__device__ float g_B1[(size_t)2 * DMODEL * HCAT];  // [e][k][n] concat, rounded
__device__ float g_B2[(size_t)2 * HCAT * DMODEL];  // [e][k][n] concat, rounded
__device__ float g_bias1[2 * HCAT];
__device__ float g_bias2[2 * DMODEL];
__device__ int   g_expert[N_TOK];
__device__ int   g_perm[N_TOK];
__device__ int   g_counts[2];
__device__ int   g_cursor[2];

__device__ __forceinline__ float rna_tf32(float f) {
    uint32_t u;
    asm("cvt.rna.tf32.f32 %0, %1;" : "=r"(u) : "f"(f));
    return __uint_as_float(u);
}

__device__ __forceinline__ void mma_tf32(float4& d, const uint32_t* a, const uint32_t* b) {
    asm volatile(
        "mma.sync.aligned.m16n8k8.row.col.f32.tf32.tf32.f32 "
        "{%0,%1,%2,%3}, {%4,%5,%6,%7}, {%8,%9}, {%0,%1,%2,%3};"
        : "+f"(d.x), "+f"(d.y), "+f"(d.z), "+f"(d.w)
        : "r"(a[0]), "r"(a[1]), "r"(a[2]), "r"(a[3]),
          "r"(b[0]), "r"(b[1]));
}

// ------------------------------------------------------------------
__global__ void zero_kernel() {
    if (threadIdx.x == 0) {
        g_counts[0] = 0; g_counts[1] = 0;
        g_cursor[0] = 0; g_cursor[1] = 0;
    }
}

// one warp per token; fp64 accumulation to make argmax robust vs reference
__global__ void gate_kernel(const float* __restrict__ x, const float* __restrict__ gw) {
    int t = blockIdx.x * (blockDim.x >> 5) + (threadIdx.x >> 5);
    if (t >= N_TOK) return;
    int lane = threadIdx.x & 31;
    const float* xr = x + (size_t)t * DMODEL;
    double s0 = 0.0, s1 = 0.0;
    for (int k = lane; k < DMODEL; k += 32) {
        double xv = (double)xr[k];
        s0 += xv * (double)gw[k];
        s1 += xv * (double)gw[DMODEL + k];
    }
    #pragma unroll
    for (int o = 16; o > 0; o >>= 1) {
        s0 += __shfl_down_sync(0xffffffffu, s0, o);
        s1 += __shfl_down_sync(0xffffffffu, s1, o);
    }
    if (lane == 0) {
        int e = (s1 > s0) ? 1 : 0;   // tie -> expert 0 (matches argmax-first)
        g_expert[t] = e;
        atomicAdd(&g_counts[e], 1);
    }
}

__global__ void scatter_kernel() {
    int t = blockIdx.x * blockDim.x + threadIdx.x;
    if (t >= N_TOK) return;
    int e = g_expert[t];
    int base = e ? g_counts[0] : 0;
    int pos = base + atomicAdd(&g_cursor[e], 1);
    g_perm[pos] = t;   // order within group irrelevant (per-token math independent)
}

__global__ void prep_x_kernel(const float* __restrict__ x) {
    const float4* x4 = reinterpret_cast<const float4*>(x);
    float4* d4 = reinterpret_cast<float4*>(g_xr);
    const int total = N_TOK * (DMODEL / 4);
    for (int i = blockIdx.x * blockDim.x + threadIdx.x; i < total;
         i += gridDim.x * blockDim.x) {
        int pos = i >> 8;          // DMODEL/4 = 256 float4 per row
        int c4  = i & 255;
        int src = g_perm[pos];
        float4 v = x4[(size_t)src * 256 + c4];
        v.x = rna_tf32(v.x); v.y = rna_tf32(v.y);
        v.z = rna_tf32(v.z); v.w = rna_tf32(v.w);
        d4[i] = v;
    }
}

__global__ void prep_B1_kernel(const float* __restrict__ w1, const float* __restrict__ sw1) {
    const float4* w14  = reinterpret_cast<const float4*>(w1);
    const float4* sw14 = reinterpret_cast<const float4*>(sw1);
    float4* d4 = reinterpret_cast<float4*>(g_B1);
    const int total = 2 * DMODEL * (HCAT / 4);   // 4194304
    for (int i = blockIdx.x * blockDim.x + threadIdx.x; i < total;
         i += gridDim.x * blockDim.x) {
        int n4 = i & 2047;           // HCAT/4
        int r  = i >> 11;
        int k  = r & 1023;
        int e  = r >> 10;
        float4 v;
        if (n4 < 1024) v = w14[((size_t)(e * DMODEL + k)) * 1024 + n4];   // w1[e][k][n]
        else           v = sw14[(size_t)k * 1024 + (n4 - 1024)];          // sw1[k][n-4096]
        v.x = rna_tf32(v.x); v.y = rna_tf32(v.y);
        v.z = rna_tf32(v.z); v.w = rna_tf32(v.w);
        d4[i] = v;
    }
}

__global__ void prep_B2_kernel(const float* __restrict__ w2, const float* __restrict__ sw2) {
    const float4* w24  = reinterpret_cast<const float4*>(w2);
    const float4* sw24 = reinterpret_cast<const float4*>(sw2);
    float4* d4 = reinterpret_cast<float4*>(g_B2);
    const int total = 2 * HCAT * (DMODEL / 4);   // 4194304
    for (int i = blockIdx.x * blockDim.x + threadIdx.x; i < total;
         i += gridDim.x * blockDim.x) {
        int n4 = i & 255;            // DMODEL/4
        int r  = i >> 8;
        int k  = r & 8191;
        int e  = r >> 13;
        float4 v;
        if (k < HID) v = w24[((size_t)(e * HID + k)) * 256 + n4];   // w2[e][k][n]
        else         v = sw24[(size_t)(k - HID) * 256 + n4];         // sw2[k-4096][n]
        v.x = rna_tf32(v.x); v.y = rna_tf32(v.y);
        v.z = rna_tf32(v.z); v.w = rna_tf32(v.w);
        d4[i] = v;
    }
}

__global__ void prep_bias1_kernel(const float* __restrict__ b1, const float* __restrict__ sb1) {
    int i = blockIdx.x * blockDim.x + threadIdx.x;
    if (i >= 2 * HCAT) return;
    int e = i >> 13;
    int n = i & (HCAT - 1);
    g_bias1[i] = (n < HID) ? b1[e * HID + n] : sb1[n - HID];
}

// bias2[e][n] = b2[e][n] + b2[1-e][n] + sb2[n] + relu(b1[1-e]) @ w2[1-e][:,n]
// The unrouted expert runs on a zero input, so its FULL output
// relu(b1_o)@w2_o + b2_o  (including b2_o!) is added to every token.
__global__ void prep_bias2_kernel(const float* __restrict__ b1, const float* __restrict__ b2,
                                  const float* __restrict__ w2, const float* __restrict__ sb2) {
    int i = blockIdx.x * blockDim.x + threadIdx.x;
    if (i >= 2 * DMODEL) return;
    int e = i >> 10;
    int n = i & (DMODEL - 1);
    int o = 1 - e;
    const float* w2o = w2 + (size_t)o * HID * DMODEL;
    const float* b1o = b1 + o * HID;
    float acc = 0.f;
    for (int k = 0; k < HID; k++)
        acc = fmaf(fmaxf(b1o[k], 0.f), w2o[(size_t)k * DMODEL + n], acc);
    g_bias2[i] = b2[e * DMODEL + n] + b2[o * DMODEL + n] + sb2[n] + acc;
}

// ------------------------------------------------------------------
// 128x128x32 double-buffered tf32 mma.sync GEMM.
// G1: A=g_xr [16384,1024], B=g_B1, N=8192, epilogue relu+rna -> g_h (sorted rows)
// !G1: A=g_h [16384,8192], B=g_B2, N=1024, epilogue +bias2 -> out[perm[row]]
template <bool G1>
__global__ void __launch_bounds__(256)
gemm_kernel(float* __restrict__ out_g2) {
    constexpr int K  = G1 ? DMODEL : HCAT;
    constexpr int NT = G1 ? HCAT : DMODEL;
    const float* __restrict__ A        = G1 ? g_xr : g_h;
    const float* __restrict__ Bfull    = G1 ? g_B1 : g_B2;
    const float* __restrict__ biasfull = G1 ? g_bias1 : g_bias2;

    // expert-group segmented m-tiling (tiles never straddle groups)
    const int c0 = g_counts[0];
    const int c1 = N_TOK - c0;
    const int t0 = (c0 + BM - 1) / BM;
    const int t1 = (c1 + BM - 1) / BM;
    int expert, row0, valid;
    {
        int mt = blockIdx.y;
        if (mt < t0)            { expert = 0; row0 = mt * BM;            valid = min(BM, c0 - row0); }
        else if (mt - t0 < t1)  { int t = mt - t0; expert = 1; row0 = c0 + t * BM; valid = min(BM, c1 - t * BM); }
        else return;
    }

    const float* __restrict__ B = Bfull + (size_t)expert * K * NT;
    const int n0 = blockIdx.x * BN;

    extern __shared__ float smem[];
    float* sA = smem;                      // [2][BK][SA_LD], stored k-major
    float* sB = smem + 2 * BK * SA_LD;     // [2][BK][SB_LD]

    const int tid  = threadIdx.x;
    const int lane = tid & 31;
    const int warp = tid >> 5;
    const int wm = warp & 1;    // 2 warps over M (64 rows each)
    const int wn = warp >> 1;   // 4 warps over N (32 cols each)

    const int a_r = tid >> 3;          // 0..31
    const int a_c = (tid & 7) << 2;    // 0,4,..28
    const int b_r = tid >> 5;          // 0..7
    const int b_c = (tid & 31) << 2;   // 0..124

    float4 a_st[4], b_st[4];

    // prologue: tile kt=0 -> smem buf 0
    #pragma unroll
    for (int p = 0; p < 4; p++) {
        int rg = row0 + a_r + p * 32; if (rg > N_TOK - 1) rg = N_TOK - 1;
        a_st[p] = *reinterpret_cast<const float4*>(A + (size_t)rg * K + a_c);
        b_st[p] = *reinterpret_cast<const float4*>(B + (size_t)(b_r + p * 8) * NT + n0 + b_c);
    }
    #pragma unroll
    for (int p = 0; p < 4; p++) {
        int r = a_r + p * 32;
        sA[(a_c + 0) * SA_LD + r] = a_st[p].x;
        sA[(a_c + 1) * SA_LD + r] = a_st[p].y;
        sA[(a_c + 2) * SA_LD + r] = a_st[p].z;
        sA[(a_c + 3) * SA_LD + r] = a_st[p].w;
        *reinterpret_cast<float4*>(&sB[(b_r + p * 8) * SB_LD + b_c]) = b_st[p];
    }
    __syncthreads();

    float4 acc[4][4];
    #pragma unroll
    for (int i = 0; i < 4; i++)
        #pragma unroll
        for (int j = 0; j < 4; j++)
            acc[i][j] = make_float4(0.f, 0.f, 0.f, 0.f);

    constexpr int KT = K / BK;
    int buf = 0;
    for (int kt = 0; kt < KT; kt++) {
        if (kt + 1 < KT) {
            #pragma unroll
            for (int p = 0; p < 4; p++) {
                int rg = row0 + a_r + p * 32; if (rg > N_TOK - 1) rg = N_TOK - 1;
                a_st[p] = *reinterpret_cast<const float4*>(
                    A + (size_t)rg * K + (kt + 1) * BK + a_c);
                b_st[p] = *reinterpret_cast<const float4*>(
                    B + (size_t)((kt + 1) * BK + b_r + p * 8) * NT + n0 + b_c);
            }
        }
        const float* cA = sA + buf * (BK * SA_LD);
        const float* cB = sB + buf * (BK * SB_LD);
        #pragma unroll
        for (int ks = 0; ks < 4; ks++) {
            uint32_t af[4][4];
            uint32_t bf[4][2];
            const int kk    = ks * 8 + (lane & 3);
            const int mbase = wm * 64 + (lane >> 2);
            const int nbase = wn * 32 + (lane >> 2);
            #pragma unroll
            for (int mt = 0; mt < 4; mt++) {
                int m = mbase + mt * 16;
                af[mt][0] = __float_as_uint(cA[kk * SA_LD + m]);
                af[mt][1] = __float_as_uint(cA[kk * SA_LD + m + 8]);
                af[mt][2] = __float_as_uint(cA[(kk + 4) * SA_LD + m]);
                af[mt][3] = __float_as_uint(cA[(kk + 4) * SA_LD + m + 8]);
            }
            #pragma unroll
            for (int nt = 0; nt < 4; nt++) {
                int n = nbase + nt * 8;
                bf[nt][0] = __float_as_uint(cB[kk * SB_LD + n]);
                bf[nt][1] = __float_as_uint(cB[(kk + 4) * SB_LD + n]);
            }
            #pragma unroll
            for (int mt = 0; mt < 4; mt++)
                #pragma unroll
                for (int nt = 0; nt < 4; nt++)
                    mma_tf32(acc[mt][nt], af[mt], bf[nt]);
        }
        if (kt + 1 < KT) {
            float* nA = sA + (buf ^ 1) * (BK * SA_LD);
            float* nB = sB + (buf ^ 1) * (BK * SB_LD);
            #pragma unroll
            for (int p = 0; p < 4; p++) {
                int r = a_r + p * 32;
                nA[(a_c + 0) * SA_LD + r] = a_st[p].x;
                nA[(a_c + 1) * SA_LD + r] = a_st[p].y;
                nA[(a_c + 2) * SA_LD + r] = a_st[p].z;
                nA[(a_c + 3) * SA_LD + r] = a_st[p].w;
                *reinterpret_cast<float4*>(&nB[(b_r + p * 8) * SB_LD + b_c]) = b_st[p];
            }
        }
        __syncthreads();
        buf ^= 1;
    }

    // epilogue
    const float* bv = biasfull + expert * NT + n0;
    const int grow = lane >> 2;
    const int gc   = (lane & 3) << 1;
    #pragma unroll
    for (int mt = 0; mt < 4; mt++) {
        int rl = wm * 64 + mt * 16 + grow;
        #pragma unroll
        for (int nt = 0; nt < 4; nt++) {
            int cl = wn * 32 + nt * 8 + gc;
            float bb0 = bv[cl], bb1 = bv[cl + 1];
            float v00 = acc[mt][nt].x + bb0;
            float v01 = acc[mt][nt].y + bb1;
            float v10 = acc[mt][nt].z + bb0;
            float v11 = acc[mt][nt].w + bb1;
            if constexpr (G1) {
                v00 = rna_tf32(fmaxf(v00, 0.f));
                v01 = rna_tf32(fmaxf(v01, 0.f));
                v10 = rna_tf32(fmaxf(v10, 0.f));
                v11 = rna_tf32(fmaxf(v11, 0.f));
                if (rl < valid) {
                    float2 v = {v00, v01};
                    *reinterpret_cast<float2*>(&g_h[(size_t)(row0 + rl) * HCAT + n0 + cl]) = v;
                }
                if (rl + 8 < valid) {
                    float2 v = {v10, v11};
                    *reinterpret_cast<float2*>(&g_h[(size_t)(row0 + rl + 8) * HCAT + n0 + cl]) = v;
                }
            } else {
                if (rl < valid) {
                    int orow = g_perm[row0 + rl];
                    float2 v = {v00, v01};
                    *reinterpret_cast<float2*>(&out_g2[(size_t)orow * DMODEL + n0 + cl]) = v;
                }
                if (rl + 8 < valid) {
                    int orow = g_perm[row0 + rl + 8];
                    float2 v = {v10, v11};
                    *reinterpret_cast<float2*>(&out_g2[(size_t)orow * DMODEL + n0 + cl]) = v;
                }
            }
        }
    }
}

// ------------------------------------------------------------------
extern "C" void kernel_launch(void* const* d_in, const int* in_sizes, int n_in,
                              void* d_out, int out_size) {
    const float* x   = (const float*)d_in[0];
    const float* gw  = (const float*)d_in[1];
    const float* w1  = (const float*)d_in[2];
    const float* b1  = (const float*)d_in[3];
    const float* w2  = (const float*)d_in[4];
    const float* b2  = (const float*)d_in[5];
    const float* sw1 = (const float*)d_in[6];
    const float* sb1 = (const float*)d_in[7];
    const float* sw2 = (const float*)d_in[8];
    const float* sb2 = (const float*)d_in[9];
    float* out = (float*)d_out;

    cudaFuncSetAttribute(gemm_kernel<true>,
                         cudaFuncAttributeMaxDynamicSharedMemorySize, SMEM_BYTES);
    cudaFuncSetAttribute(gemm_kernel<false>,
                         cudaFuncAttributeMaxDynamicSharedMemorySize, SMEM_BYTES);

    zero_kernel<<<1, 32>>>();
    gate_kernel<<<N_TOK / 8, 256>>>(x, gw);           // 8 warps/block, 1 warp/token
    scatter_kernel<<<N_TOK / 256, 256>>>();
    prep_x_kernel<<<2048, 256>>>(x);
    prep_B1_kernel<<<2048, 256>>>(w1, sw1);
    prep_B2_kernel<<<2048, 256>>>(w2, sw2);
    prep_bias1_kernel<<<(2 * HCAT) / 256, 256>>>(b1, sb1);
    prep_bias2_kernel<<<(2 * DMODEL) / 256, 256>>>(b1, b2, w2, sb2);

    constexpr int MT = (N_TOK + BM - 1) / BM + 1;     // 129: groups may each pad one tile
    gemm_kernel<true ><<<dim3(HCAT / BN,   MT), 256, SMEM_BYTES>>>(nullptr);
    gemm_kernel<false><<<dim3(DMODEL / BN, MT), 256, SMEM_BYTES>>>(out);
}

// round 8
// speedup vs baseline: 1.2430x; 1.2430x over previous
#include <cuda_runtime.h>
#include <cstdint>

// DeepSeekMoEFFN on GB300 (plain sm_103 PTX target -> no tcgen05; use
// mma.sync tf32 with a cp.async 3-stage pipeline instead).
//
//  1. gate (fp64 argmax) -> expert ids + counts
//  2. counting-sort -> perm
//  3. prep: gather+rna(x); transpose+rna weights to K-major [e][n][k];
//     bias1=[b1_e|sb1]; bias2 = b2_0+b2_1+sb2+relu(b1_o)@w2_o
//  4. GEMM1: h = rna(relu(xs @ B1_e + bias1_e))   [16384 x 8192]
//  5. GEMM2: out[perm] = h @ B2_e + bias2_e       [16384 x 1024]

#define N_TOK  16384
#define DMODEL 1024
#define HID    4096
#define HCAT   8192

#define BM 128
#define BN 128
#define BK 32
#define STAGES 3
#define LDK 36                         // padded k-stride (floats): conflict-free
#define STG_F (BM * LDK)               // 4608 floats per operand stage
#define GEMM_SMEM (STAGES * 2 * STG_F * 4)   // 110592 B

// ---- static device scratch ----
__device__ float g_h [(size_t)N_TOK * HCAT];      // intermediate (tf32-rounded)
__device__ float g_xr[(size_t)N_TOK * DMODEL];    // sorted + rounded x
__device__ float g_B1[(size_t)2 * HCAT * DMODEL]; // [e][n][k] K-major, rounded
__device__ float g_B2[(size_t)2 * DMODEL * HCAT]; // [e][n][k] K-major, rounded
__device__ float g_bias1[2 * HCAT];
__device__ float g_bias2[2 * DMODEL];
__device__ int   g_expert[N_TOK];
__device__ int   g_perm[N_TOK];
__device__ int   g_counts[2];
__device__ int   g_cursor[2];

// ---------------- helpers ----------------
__device__ __forceinline__ float rna_tf32(float f) {
    uint32_t u;
    asm("cvt.rna.tf32.f32 %0, %1;" : "=r"(u) : "f"(f));
    return __uint_as_float(u);
}
__device__ __forceinline__ void mma_tf32(float4& d, const uint32_t* a, const uint32_t* b) {
    asm volatile(
        "mma.sync.aligned.m16n8k8.row.col.f32.tf32.tf32.f32 "
        "{%0,%1,%2,%3}, {%4,%5,%6,%7}, {%8,%9}, {%0,%1,%2,%3};"
        : "+f"(d.x), "+f"(d.y), "+f"(d.z), "+f"(d.w)
        : "r"(a[0]), "r"(a[1]), "r"(a[2]), "r"(a[3]),
          "r"(b[0]), "r"(b[1]));
}
__device__ __forceinline__ void cp_async16(uint32_t s, const void* g) {
    asm volatile("cp.async.cg.shared.global [%0], [%1], 16;" :: "r"(s), "l"(g));
}
#define CP_COMMIT() asm volatile("cp.async.commit_group;" ::: "memory")
#define CP_WAIT1()  asm volatile("cp.async.wait_group 1;" ::: "memory")

// ---------------- routing / prep ----------------
__global__ void zero_kernel() {
    if (threadIdx.x == 0) { g_counts[0] = g_counts[1] = 0; g_cursor[0] = g_cursor[1] = 0; }
}

__global__ void gate_kernel(const float* __restrict__ x, const float* __restrict__ gw) {
    int t = blockIdx.x * (blockDim.x >> 5) + (threadIdx.x >> 5);
    if (t >= N_TOK) return;
    int lane = threadIdx.x & 31;
    const float* xr = x + (size_t)t * DMODEL;
    double s0 = 0.0, s1 = 0.0;
    for (int k = lane; k < DMODEL; k += 32) {
        double xv = (double)xr[k];
        s0 += xv * (double)gw[k];
        s1 += xv * (double)gw[DMODEL + k];
    }
    #pragma unroll
    for (int o = 16; o > 0; o >>= 1) {
        s0 += __shfl_down_sync(0xffffffffu, s0, o);
        s1 += __shfl_down_sync(0xffffffffu, s1, o);
    }
    if (lane == 0) {
        int e = (s1 > s0) ? 1 : 0;
        g_expert[t] = e;
        atomicAdd(&g_counts[e], 1);
    }
}

__global__ void scatter_kernel() {
    int t = blockIdx.x * blockDim.x + threadIdx.x;
    if (t >= N_TOK) return;
    int e = g_expert[t];
    int base = e ? g_counts[0] : 0;
    g_perm[base + atomicAdd(&g_cursor[e], 1)] = t;
}

__global__ void prep_x_kernel(const float* __restrict__ x) {
    const float4* x4 = reinterpret_cast<const float4*>(x);
    float4* d4 = reinterpret_cast<float4*>(g_xr);
    const int total = N_TOK * (DMODEL / 4);
    for (int i = blockIdx.x * blockDim.x + threadIdx.x; i < total;
         i += gridDim.x * blockDim.x) {
        int pos = i >> 8, c4 = i & 255;
        int src = g_perm[pos];
        float4 v = x4[(size_t)src * 256 + c4];
        v.x = rna_tf32(v.x); v.y = rna_tf32(v.y);
        v.z = rna_tf32(v.z); v.w = rna_tf32(v.w);
        d4[i] = v;
    }
}

// B1t[e][n][k] = rna( n<HID ? w1[e][k][n] : sw1[k][n-HID] )
__global__ void prep_B1t_kernel(const float* __restrict__ w1, const float* __restrict__ sw1) {
    __shared__ float t[32][33];
    int n0 = blockIdx.x * 32, k0 = blockIdx.y * 32, e = blockIdx.z;
    int tx = threadIdx.x & 31, ty = threadIdx.x >> 5;
    int n = n0 + tx;
    #pragma unroll
    for (int p = 0; p < 4; p++) {
        int k = k0 + ty + p * 8;
        float v = (n < HID) ? w1[((size_t)e * DMODEL + k) * HID + n]
                            : sw1[(size_t)k * HID + (n - HID)];
        t[ty + p * 8][tx] = rna_tf32(v);
    }
    __syncthreads();
    #pragma unroll
    for (int p = 0; p < 4; p++) {
        int ni = ty + p * 8;
        g_B1[((size_t)e * HCAT + n0 + ni) * DMODEL + k0 + tx] = t[tx][ni];
    }
}

// B2t[e][n][k] = rna( k<HID ? w2[e][k][n] : sw2[k-HID][n] )
__global__ void prep_B2t_kernel(const float* __restrict__ w2, const float* __restrict__ sw2) {
    __shared__ float t[32][33];
    int n0 = blockIdx.x * 32, k0 = blockIdx.y * 32, e = blockIdx.z;
    int tx = threadIdx.x & 31, ty = threadIdx.x >> 5;
    int n = n0 + tx;
    #pragma unroll
    for (int p = 0; p < 4; p++) {
        int k = k0 + ty + p * 8;
        float v = (k < HID) ? w2[((size_t)e * HID + k) * DMODEL + n]
                            : sw2[(size_t)(k - HID) * DMODEL + n];
        t[ty + p * 8][tx] = rna_tf32(v);
    }
    __syncthreads();
    #pragma unroll
    for (int p = 0; p < 4; p++) {
        int ni = ty + p * 8;
        g_B2[((size_t)e * DMODEL + n0 + ni) * HCAT + k0 + tx] = t[tx][ni];
    }
}

__global__ void prep_bias1_kernel(const float* __restrict__ b1, const float* __restrict__ sb1) {
    int i = blockIdx.x * blockDim.x + threadIdx.x;
    if (i >= 2 * HCAT) return;
    int e = i >> 13, n = i & (HCAT - 1);
    g_bias1[i] = (n < HID) ? b1[e * HID + n] : sb1[n - HID];
}

// bias2[e][n] = b2[e][n] + b2[1-e][n] + sb2[n] + relu(b1[1-e]) @ w2[1-e][:,n]
__global__ void prep_bias2_kernel(const float* __restrict__ b1, const float* __restrict__ b2,
                                  const float* __restrict__ w2, const float* __restrict__ sb2) {
    int i = blockIdx.x * blockDim.x + threadIdx.x;
    if (i >= 2 * DMODEL) return;
    int e = i >> 10, n = i & (DMODEL - 1);
    int o = 1 - e;
    const float* w2o = w2 + (size_t)o * HID * DMODEL;
    const float* b1o = b1 + o * HID;
    float acc = 0.f;
    for (int k = 0; k < HID; k++)
        acc = fmaf(fmaxf(b1o[k], 0.f), w2o[(size_t)k * DMODEL + n], acc);
    g_bias2[i] = b2[e * DMODEL + n] + b2[o * DMODEL + n] + sb2[n] + acc;
}

// ------------------------------------------------------------------
// 128x128x32 tf32 mma.sync GEMM, 3-stage cp.async pipeline, 2 CTAs/SM.
// A smem [m][k] stride 36, B smem [n][k] stride 36 (both conflict-free).
// G1: A=g_xr (K=1024), B=g_B1 (NT=8192) -> relu+rna -> g_h
// !G1: A=g_h (K=8192), B=g_B2 (NT=1024) -> +bias2 -> out[perm]
template <int K, int NT, bool G1>
__global__ void __launch_bounds__(256, 2)
gemm_cp(float* __restrict__ out_g2) {
    // CTA raster swizzle: groups of 16 m-tiles, m fastest within a group
    const int bid = blockIdx.y * gridDim.x + blockIdx.x;
    const int per = gridDim.x * 16;
    const int mt  = (bid / per) * 16 + (bid % 16);
    const int j   = (bid % per) >> 4;

    // expert-group segmented m-tiles
    const int c0 = g_counts[0];
    const int c1 = N_TOK - c0;
    const int t0 = (c0 + BM - 1) / BM;
    const int t1 = (c1 + BM - 1) / BM;
    int expert, row0, valid;
    if (mt < t0)           { expert = 0; row0 = mt * BM;            valid = min(BM, c0 - row0); }
    else if (mt - t0 < t1) { int t = mt - t0; expert = 1; row0 = c0 + t * BM; valid = min(BM, c1 - t * BM); }
    else return;

    const float* __restrict__ A    = G1 ? g_xr : g_h;
    const float* __restrict__ Bt   = G1 ? g_B1 : g_B2;
    const float* __restrict__ bias = G1 ? g_bias1 : g_bias2;
    const int n0 = j * BN;
    const float* __restrict__ Bp = Bt + ((size_t)expert * NT + n0) * K;

    extern __shared__ float smem[];
    float* sA = smem;                    // [STAGES][BM][LDK]
    float* sB = smem + STAGES * STG_F;   // [STAGES][BN][LDK]
    const uint32_t sAu = (uint32_t)__cvta_generic_to_shared(sA);
    const uint32_t sBu = (uint32_t)__cvta_generic_to_shared(sB);

    const int tid = threadIdx.x, lane = tid & 31, warp = tid >> 5;
    const int wm = warp & 1;    // 2 warps over M (64 rows)
    const int wn = warp >> 1;   // 4 warps over N (32 cols)

    // cp.async fill: per stage A 128x32f (4x16B/thr), B 128x32f (4x16B/thr)
    auto load_tile = [&](int kt, int stage) {
        const int kof = kt * BK;
        const uint32_t aB = sAu + stage * (STG_F * 4);
        const uint32_t bB = sBu + stage * (STG_F * 4);
        #pragma unroll
        for (int p = 0; p < 4; p++) {
            int idx = tid + p * 256;             // 0..1023
            int r = idx >> 3, c4 = idx & 7;
            int rg = row0 + r; if (rg > N_TOK - 1) rg = N_TOK - 1;
            cp_async16(aB + (uint32_t)(r * (LDK * 4) + c4 * 16),
                       A + (size_t)rg * K + kof + c4 * 4);
            cp_async16(bB + (uint32_t)(r * (LDK * 4) + c4 * 16),
                       Bp + (size_t)r * K + kof + c4 * 4);
        }
        CP_COMMIT();
    };

    constexpr int KT = K / BK;
    load_tile(0, 0);
    load_tile(1, 1);

    float4 acc[4][4];
    #pragma unroll
    for (int i = 0; i < 4; i++)
        #pragma unroll
        for (int jn = 0; jn < 4; jn++)
            acc[i][jn] = make_float4(0.f, 0.f, 0.f, 0.f);

    const int mbase = wm * 64 + (lane >> 2);
    const int nbase = wn * 32 + (lane >> 2);
    const int kl    = lane & 3;

    #pragma unroll 1
    for (int kt = 0; kt < KT; kt++) {
        CP_WAIT1();
        __syncthreads();
        // prefetch stage kt+2 (overwrites stage consumed at kt-1; sync above fences it)
        if (kt + 2 < KT) load_tile(kt + 2, (kt + 2) % STAGES);
        else             CP_COMMIT();          // keep group arithmetic uniform

        const float* cA = sA + (kt % STAGES) * STG_F;
        const float* cB = sB + (kt % STAGES) * STG_F;
        #pragma unroll
        for (int ks = 0; ks < 4; ks++) {
            const int kk = ks * 8 + kl;
            uint32_t af[4][4], bf[4][2];
            #pragma unroll
            for (int mtl = 0; mtl < 4; mtl++) {
                int m = mbase + mtl * 16;
                af[mtl][0] = __float_as_uint(cA[m * LDK + kk]);
                af[mtl][1] = __float_as_uint(cA[(m + 8) * LDK + kk]);
                af[mtl][2] = __float_as_uint(cA[m * LDK + kk + 4]);
                af[mtl][3] = __float_as_uint(cA[(m + 8) * LDK + kk + 4]);
            }
            #pragma unroll
            for (int nt = 0; nt < 4; nt++) {
                int n = nbase + nt * 8;
                bf[nt][0] = __float_as_uint(cB[n * LDK + kk]);
                bf[nt][1] = __float_as_uint(cB[n * LDK + kk + 4]);
            }
            #pragma unroll
            for (int mtl = 0; mtl < 4; mtl++)
                #pragma unroll
                for (int nt = 0; nt < 4; nt++)
                    mma_tf32(acc[mtl][nt], af[mtl], bf[nt]);
        }
    }

    // epilogue
    const float* bv = bias + (size_t)expert * NT + n0;
    const int grow = lane >> 2;
    const int gc   = (lane & 3) << 1;
    #pragma unroll
    for (int mtl = 0; mtl < 4; mtl++) {
        int rl = wm * 64 + mtl * 16 + grow;
        #pragma unroll
        for (int nt = 0; nt < 4; nt++) {
            int cl = wn * 32 + nt * 8 + gc;
            float bb0 = bv[cl], bb1 = bv[cl + 1];
            float v00 = acc[mtl][nt].x + bb0;
            float v01 = acc[mtl][nt].y + bb1;
            float v10 = acc[mtl][nt].z + bb0;
            float v11 = acc[mtl][nt].w + bb1;
            if constexpr (G1) {
                v00 = rna_tf32(fmaxf(v00, 0.f));
                v01 = rna_tf32(fmaxf(v01, 0.f));
                v10 = rna_tf32(fmaxf(v10, 0.f));
                v11 = rna_tf32(fmaxf(v11, 0.f));
                if (rl < valid) {
                    float2 v = {v00, v01};
                    *reinterpret_cast<float2*>(&g_h[(size_t)(row0 + rl) * HCAT + n0 + cl]) = v;
                }
                if (rl + 8 < valid) {
                    float2 v = {v10, v11};
                    *reinterpret_cast<float2*>(&g_h[(size_t)(row0 + rl + 8) * HCAT + n0 + cl]) = v;
                }
            } else {
                if (rl < valid) {
                    int orow = g_perm[row0 + rl];
                    float2 v = {v00, v01};
                    *reinterpret_cast<float2*>(&out_g2[(size_t)orow * DMODEL + n0 + cl]) = v;
                }
                if (rl + 8 < valid) {
                    int orow = g_perm[row0 + rl + 8];
                    float2 v = {v10, v11};
                    *reinterpret_cast<float2*>(&out_g2[(size_t)orow * DMODEL + n0 + cl]) = v;
                }
            }
        }
    }
}

// ---------------- launch ----------------
extern "C" void kernel_launch(void* const* d_in, const int* in_sizes, int n_in,
                              void* d_out, int out_size) {
    const float* x   = (const float*)d_in[0];
    const float* gw  = (const float*)d_in[1];
    const float* w1  = (const float*)d_in[2];
    const float* b1  = (const float*)d_in[3];
    const float* w2  = (const float*)d_in[4];
    const float* b2  = (const float*)d_in[5];
    const float* sw1 = (const float*)d_in[6];
    const float* sb1 = (const float*)d_in[7];
    const float* sw2 = (const float*)d_in[8];
    const float* sb2 = (const float*)d_in[9];
    float* out = (float*)d_out;

    cudaFuncSetAttribute((const void*)gemm_cp<DMODEL, HCAT, true>,
                         cudaFuncAttributeMaxDynamicSharedMemorySize, GEMM_SMEM);
    cudaFuncSetAttribute((const void*)gemm_cp<HCAT, DMODEL, false>,
                         cudaFuncAttributeMaxDynamicSharedMemorySize, GEMM_SMEM);

    zero_kernel<<<1, 32>>>();
    gate_kernel<<<N_TOK / 8, 256>>>(x, gw);
    scatter_kernel<<<N_TOK / 256, 256>>>();
    prep_x_kernel<<<2048, 256>>>(x);
    prep_B1t_kernel<<<dim3(HCAT / 32, DMODEL / 32, 2), 256>>>(w1, sw1);
    prep_B2t_kernel<<<dim3(DMODEL / 32, HCAT / 32, 2), 256>>>(w2, sw2);
    prep_bias1_kernel<<<(2 * HCAT) / 256, 256>>>(b1, sb1);
    prep_bias2_kernel<<<(2 * DMODEL) / 256, 256>>>(b1, b2, w2, sb2);

    // 129 m-tiles padded to 144 (9 swizzle groups of 16); extras exit early
    gemm_cp<DMODEL, HCAT, true ><<<dim3(HCAT / BN,   144), 256, GEMM_SMEM>>>(nullptr);
    gemm_cp<HCAT, DMODEL, false><<<dim3(DMODEL / BN, 144), 256, GEMM_SMEM>>>(out);
}